// round 6
// baseline (speedup 1.0000x reference)
#include <cuda_runtime.h>
#include <cstdint>

#define SQ 1024
#define HD 64
#define TQ 128         // query rows per CTA (8 warps x 16 rows, pure M split)
#define CK 32          // key cols per chunk
#define NCH (SQ / CK)  // 32
#define NTHREADS 256

// smem: K/V double buffer only (+invs). K [64d][32s] pitch 40, V [32s][64d] pitch 72.
#define KP 40
#define VP 72
#define KVBUF 4864     // 64*40 + 32*72
#define VOFF 2560
#define QSP 68         // one-time raw-Q staging pitch (overlays KV buffers)
#define OFF_INV 9728
#define SMEM_FLOATS (OFF_INV + 128)   // 9856 floats = 39424 B

__device__ __forceinline__ unsigned f2tf32(float v) {
    unsigned r;
    asm("cvt.rna.tf32.f32 %0, %1;" : "=r"(r) : "f"(v));
    return r;
}

__device__ __forceinline__ void mma16x8x8(float* c, const unsigned* a, const unsigned* b) {
    asm volatile(
        "mma.sync.aligned.m16n8k8.row.col.f32.tf32.tf32.f32 "
        "{%0,%1,%2,%3}, {%4,%5,%6,%7}, {%8,%9}, {%0,%1,%2,%3};\n"
        : "+f"(c[0]), "+f"(c[1]), "+f"(c[2]), "+f"(c[3])
        : "r"(a[0]), "r"(a[1]), "r"(a[2]), "r"(a[3]),
          "r"(b[0]), "r"(b[1]));
}

__device__ __forceinline__ void cp16(uint32_t dst, const void* src) {
    asm volatile("cp.async.cg.shared.global [%0], [%1], 16;" :: "r"(dst), "l"(src));
}
__device__ __forceinline__ void cp_commit() {
    asm volatile("cp.async.commit_group;" ::: "memory");
}
template<int N> __device__ __forceinline__ void cp_wait() {
    asm volatile("cp.async.wait_group %0;" :: "n"(N) : "memory");
}

__global__ __launch_bounds__(NTHREADS, 2)
void attn_k6_kernel(const float* __restrict__ q, const float* __restrict__ k,
                    const float* __restrict__ v, const float* __restrict__ prev,
                    const float* __restrict__ mask, const float* __restrict__ scale_p,
                    float* __restrict__ out, float* __restrict__ wts,
                    float* __restrict__ scr)
{
    extern __shared__ float smem[];
    const uint32_t sbase = (uint32_t)__cvta_generic_to_shared(smem);
    float* invs = smem + OFF_INV;

    const int bh  = blockIdx.y;
    const int q0  = blockIdx.x * TQ;
    const int tid = threadIdx.x;
    const int wid = tid >> 5;        // 0..7, pure M split (16 rows each)
    const int lane = tid & 31;
    const int gID = lane >> 2;       // 0..7
    const int tig = lane & 3;        // 0..3
    const int r0  = wid * 16 + gID;
    const int r1  = r0 + 8;
    const int gr0 = q0 + r0;
    const int gr1 = q0 + r1;
    const int l_lo = (lane & 28) | (tig >> 1);   // quad-base + tig/2
    const int l_hi = l_lo + 2;
    const bool odd = (tig & 1);

    const float scale = __ldg(scale_p);

    const float* qh = q    + (size_t)bh * SQ * HD;
    const float* kh = k    + (size_t)bh * HD * SQ;   // [D][S]
    const float* vh = v    + (size_t)bh * SQ * HD;
    const float* ph = prev + (size_t)bh * SQ * SQ;
    float* outh = out + (size_t)bh * SQ * HD;
    float* wh   = wts + (size_t)bh * SQ * SQ;
    float* shh  = scr + (size_t)bh * SQ * SQ;

    // ---- stage K,V for chunk ch into buffer buf (4 cp16 per thread) ----
    auto stage_chunk = [&](int ch, int buf) {
        const int s0 = ch * CK;
        const int kvb = buf * KVBUF;
        #pragma unroll
        for (int j = 0; j < 2; j++) {          // K [64 d][32 s]
            int i = tid + j * NTHREADS;
            int r = i >> 3, c = (i & 7) << 2;
            cp16(sbase + (uint32_t)(kvb + r * KP + c) * 4,
                 kh + (size_t)r * SQ + s0 + c);
        }
        #pragma unroll
        for (int j = 0; j < 2; j++) {          // V [32 s][64 d]
            int i = tid + j * NTHREADS;
            int r = i >> 4, c = (i & 15) << 2;
            cp16(sbase + (uint32_t)(kvb + VOFF + r * VP + c) * 4,
                 vh + (size_t)(s0 + r) * HD + c);
        }
    };

    // ---- prologue: raw Q -> smem (overlaying KV area), extract frags to regs ----
    #pragma unroll
    for (int j = 0; j < 8; j++) {
        int i = tid + j * NTHREADS;            // float4 index over 128x64 Q
        int r = i >> 4, c4 = (i & 15) << 2;
        cp16(sbase + (uint32_t)(r * QSP + c4) * 4,
             qh + (size_t)(q0 + r) * HD + c4);
    }
    cp_commit();
    cp_wait<0>();
    __syncthreads();

    unsigned qf[8][4];
    #pragma unroll
    for (int kk = 0; kk < 8; kk++) {
        const int d0 = kk * 8;
        qf[kk][0] = f2tf32(smem[r0 * QSP + d0 + tig]);
        qf[kk][1] = f2tf32(smem[r1 * QSP + d0 + tig]);
        qf[kk][2] = f2tf32(smem[r0 * QSP + d0 + tig + 4]);
        qf[kk][3] = f2tf32(smem[r1 * QSP + d0 + tig + 4]);
    }
    __syncthreads();       // Q consumed -> KV buffers reusable

    stage_chunk(0, 0);
    cp_commit();

    // prev prefetch (chunk 0) into registers
    float2 nx0[4], nx1[4];
    #pragma unroll
    for (int n = 0; n < 4; n++) {
        const int col = n * 8 + tig * 2;
        nx0[n] = *(const float2*)(ph + (size_t)gr0 * SQ + col);
        nx1[n] = *(const float2*)(ph + (size_t)gr1 * SQ + col);
    }

    float oacc[8][4];
    #pragma unroll
    for (int m = 0; m < 8; m++) {
        oacc[m][0] = 0.f; oacc[m][1] = 0.f; oacc[m][2] = 0.f; oacc[m][3] = 0.f;
    }
    float ls0 = 0.f, ls1 = 0.f;

    for (int ch = 0; ch < NCH; ch++) {
        const int buf = ch & 1;
        const int s0 = ch * CK;
        const float* Ks = smem + buf * KVBUF;
        const float* Vs = Ks + VOFF;

        cp_wait<0>();          // chunk ch landed (single group in flight)
        __syncthreads();       // all warps done with buf^1 reads -> staging safe

        if (ch + 1 < NCH) {
            stage_chunk(ch + 1, buf ^ 1);
            cp_commit();
        }

        float2 pv0[4], pv1[4];
        #pragma unroll
        for (int n = 0; n < 4; n++) { pv0[n] = nx0[n]; pv1[n] = nx1[n]; }
        if (ch + 1 < NCH) {
            const int sn = (ch + 1) * CK;
            #pragma unroll
            for (int n = 0; n < 4; n++) {
                const int col = sn + n * 8 + tig * 2;
                nx0[n] = *(const float2*)(ph + (size_t)gr0 * SQ + col);
                nx1[n] = *(const float2*)(ph + (size_t)gr1 * SQ + col);
            }
        }

        // ---- mma1: S(16x32) = Q(16x64) @ K(64x32), A from registers ----
        float acc[4][4];
        #pragma unroll
        for (int n = 0; n < 4; n++) {
            acc[n][0] = 0.f; acc[n][1] = 0.f; acc[n][2] = 0.f; acc[n][3] = 0.f;
        }
        #pragma unroll
        for (int kk = 0; kk < 8; kk++) {
            const int d0 = kk * 8;
            #pragma unroll
            for (int n = 0; n < 4; n++) {
                unsigned b[2];
                b[0] = f2tf32(Ks[(d0 + tig) * KP + n * 8 + gID]);
                b[1] = f2tf32(Ks[(d0 + tig + 4) * KP + n * 8 + gID]);
                mma16x8x8(acc[n], qf[kk], b);
            }
        }

        // ---- epilogue: scores -> gmem, exp -> regs, rowsums (warp-local) ----
        float E[4][4];
        #pragma unroll
        for (int n = 0; n < 4; n++) {
            const int col = s0 + n * 8 + tig * 2;
            float2 mk0 = *(const float2*)(mask + (size_t)gr0 * SQ + col);
            float2 mk1 = *(const float2*)(mask + (size_t)gr1 * SQ + col);
            float s00 = acc[n][0] * mk0.x * scale + pv0[n].x;
            float s01 = acc[n][1] * mk0.y * scale + pv0[n].y;
            float s10 = acc[n][2] * mk1.x * scale + pv1[n].x;
            float s11 = acc[n][3] * mk1.y * scale + pv1[n].y;
            *(float2*)(shh + (size_t)gr0 * SQ + col) = make_float2(s00, s01);
            *(float2*)(shh + (size_t)gr1 * SQ + col) = make_float2(s10, s11);
            float e00 = __expf(s00), e01 = __expf(s01);
            float e10 = __expf(s10), e11 = __expf(s11);
            ls0 += e00 + e01;
            ls1 += e10 + e11;
            E[n][0] = __uint_as_float(f2tf32(e00));
            E[n][1] = __uint_as_float(f2tf32(e01));
            E[n][2] = __uint_as_float(f2tf32(e10));
            E[n][3] = __uint_as_float(f2tf32(e11));
        }

        // ---- mma2: out += E(16x32) @ V(32x64); A via register shuffle (C->A perm) ----
        #pragma unroll
        for (int n = 0; n < 4; n++) {
            float v0, v1;
            v0 = __shfl_sync(0xffffffffu, E[n][0], l_lo);
            v1 = __shfl_sync(0xffffffffu, E[n][1], l_lo);
            float a0 = odd ? v1 : v0;
            v0 = __shfl_sync(0xffffffffu, E[n][0], l_hi);
            v1 = __shfl_sync(0xffffffffu, E[n][1], l_hi);
            float a2 = odd ? v1 : v0;
            v0 = __shfl_sync(0xffffffffu, E[n][2], l_lo);
            v1 = __shfl_sync(0xffffffffu, E[n][3], l_lo);
            float a1 = odd ? v1 : v0;
            v0 = __shfl_sync(0xffffffffu, E[n][2], l_hi);
            v1 = __shfl_sync(0xffffffffu, E[n][3], l_hi);
            float a3 = odd ? v1 : v0;
            unsigned ua[4] = { __float_as_uint(a0), __float_as_uint(a1),
                               __float_as_uint(a2), __float_as_uint(a3) };
            const int k0 = n * 8;
            #pragma unroll
            for (int m = 0; m < 8; m++) {
                unsigned b[2];
                b[0] = f2tf32(Vs[(k0 + tig) * VP + m * 8 + gID]);
                b[1] = f2tf32(Vs[(k0 + tig + 4) * VP + m * 8 + gID]);
                mma16x8x8(oacc[m], ua, b);
            }
        }
    }

    // ---- rowsums (quad-local) -> invs ----
    ls0 += __shfl_xor_sync(0xffffffffu, ls0, 1);
    ls0 += __shfl_xor_sync(0xffffffffu, ls0, 2);
    ls1 += __shfl_xor_sync(0xffffffffu, ls1, 1);
    ls1 += __shfl_xor_sync(0xffffffffu, ls1, 2);
    const float inv0 = 1.0f / ls0;
    const float inv1 = 1.0f / ls1;
    if (tig == 0) {
        invs[r0] = inv0;
        invs[r1] = inv1;
    }

    // ---- write output (normalized) ----
    #pragma unroll
    for (int m = 0; m < 8; m++) {
        const int col = m * 8 + tig * 2;
        *(float2*)(outh + (size_t)gr0 * HD + col) =
            make_float2(oacc[m][0] * inv0, oacc[m][1] * inv0);
        *(float2*)(outh + (size_t)gr1 * HD + col) =
            make_float2(oacc[m][2] * inv1, oacc[m][3] * inv1);
    }
    __syncthreads();

    // ---- weights tail: w = exp(score) * inv (streaming float4) ----
    #pragma unroll 4
    for (int i = tid; i < TQ * (SQ / 4); i += NTHREADS) {
        int r  = i >> 8;                 // 256 float4 per row
        int c4 = (i & 255) << 2;
        const float iv = invs[r];
        float4 s = *(const float4*)(shh + (size_t)(q0 + r) * SQ + c4);
        float4 w;
        w.x = __expf(s.x) * iv; w.y = __expf(s.y) * iv;
        w.z = __expf(s.z) * iv; w.w = __expf(s.w) * iv;
        *(float4*)(wh + (size_t)(q0 + r) * SQ + c4) = w;
    }
}

extern "C" void kernel_launch(void* const* d_in, const int* in_sizes, int n_in,
                              void* d_out, int out_size) {
    const float* q     = (const float*)d_in[0];
    const float* k     = (const float*)d_in[1];
    const float* v     = (const float*)d_in[2];
    const float* prev  = (const float*)d_in[3];
    const float* mask  = (const float*)d_in[4];
    const float* scale = (const float*)d_in[5];

    float* out = (float*)d_out;
    float* wts = out + (size_t)8 * 16 * 1024 * 64;
    float* scr = wts + (size_t)8 * 16 * 1024 * 1024;

    const size_t smem_bytes = (size_t)SMEM_FLOATS * sizeof(float);   // 39424 B
    cudaFuncSetAttribute(attn_k6_kernel,
                         cudaFuncAttributeMaxDynamicSharedMemorySize, (int)smem_bytes);

    dim3 grid(SQ / TQ, 8 * 16);   // (8 q-tiles, 128 bh)
    attn_k6_kernel<<<grid, NTHREADS, smem_bytes>>>(q, k, v, prev, mask, scale,
                                                   out, wts, scr);
}